// round 14
// baseline (speedup 1.0000x reference)
#include <cuda_runtime.h>
#include <cuda_fp16.h>
#include <cstdint>
#include <math.h>

// ---------------------------------------------------------------------------
// Problem constants
// ---------------------------------------------------------------------------
#define BSZ 16
#define SEQ 1024
#define DMODEL 768
#define NHEAD 12
#define EDIM 64
#define SOFTMAX_DIV 27.712812921102035f
#define LOG2E 1.4426950408889634f

#define BHNE (BSZ * NHEAD * SEQ * EDIM)
__device__ __half g_Q[BHNE];                    // pre-scaled by log2(e)
__device__ __half g_K[BHNE];
__device__ __half g_V[BHNE];
__device__ __half g_O2[BSZ * SEQ * DMODEL];     // dense concat matrix

// pre-converted fp16 operands
__device__ __half g_xt[BSZ * SEQ * DMODEL];
__device__ __half g_wqkt[2 * DMODEL * DMODEL];
__device__ __half g_wvt[DMODEL * DMODEL];
__device__ __half g_wot[DMODEL * DMODEL];

// ---------------------------------------------------------------------------
// helpers (plain sm_80+ PTX only)
// ---------------------------------------------------------------------------
__device__ __forceinline__ uint32_t smem_u32(const void* p) {
    uint32_t a;
    asm("{ .reg .u64 t; cvta.to.shared.u64 t, %1; cvt.u32.u64 %0, t; }"
        : "=r"(a) : "l"(p));
    return a;
}
__device__ __forceinline__ void cpa16(uint32_t dst, const void* src) {
    asm volatile("cp.async.cg.shared.global [%0], [%1], 16;"
                 :: "r"(dst), "l"(src));
}
#define CP_COMMIT() asm volatile("cp.async.commit_group;" ::: "memory")
#define CP_WAIT0()  asm volatile("cp.async.wait_group 0;" ::: "memory")
#define CP_WAIT1()  asm volatile("cp.async.wait_group 1;" ::: "memory")

__device__ __forceinline__ float ex2(float x) {
    float y;
    asm("ex2.approx.f32 %0, %1;" : "=f"(y) : "f"(x));
    return y;
}

#define MMA_F16(acc, af, bf)                                                   \
    asm volatile(                                                              \
        "mma.sync.aligned.m16n8k16.row.col.f32.f16.f16.f32 "                   \
        "{%0,%1,%2,%3}, {%4,%5,%6,%7}, {%8,%9}, {%0,%1,%2,%3};"                \
        : "+f"((acc)[0]), "+f"((acc)[1]), "+f"((acc)[2]), "+f"((acc)[3])       \
        : "r"((af)[0]), "r"((af)[1]), "r"((af)[2]), "r"((af)[3]),              \
          "r"((bf)[0]), "r"((bf)[1]))

__device__ __forceinline__ void ldm_x4(uint32_t* r, uint32_t addr) {
    asm volatile(
        "ldmatrix.sync.aligned.m8n8.x4.shared.b16 {%0,%1,%2,%3}, [%4];"
        : "=r"(r[0]), "=r"(r[1]), "=r"(r[2]), "=r"(r[3]) : "r"(addr));
}
__device__ __forceinline__ void ldm_x4_t(uint32_t* r, uint32_t addr) {
    asm volatile(
        "ldmatrix.sync.aligned.m8n8.x4.trans.shared.b16 {%0,%1,%2,%3}, [%4];"
        : "=r"(r[0]), "=r"(r[1]), "=r"(r[2]), "=r"(r[3]) : "r"(addr));
}
// A-style x4: matrices (R,k0),(R+8,k0),(R,k8),(R+8,k8)  (ST in halves)
__device__ __forceinline__ uint32_t lda_off_h(int lane, int ST) {
    int row = (lane & 7) + ((lane >> 3) & 1) * 8;
    int koff = ((lane >> 4) & 1) * 8;
    return (uint32_t)((row * ST + koff) * 2);
}
// B-style x4: matrices (N,k0),(N,k8),(N+8,k0),(N+8,k8)
__device__ __forceinline__ uint32_t ldb_off_h(int lane, int ST) {
    int row = (lane & 7) + ((lane >> 4) & 1) * 8;
    int koff = ((lane >> 3) & 1) * 8;
    return (uint32_t)((row * ST + koff) * 2);
}
__device__ __forceinline__ uint32_t packh2(float a, float b) {
    __half2 h = __floats2half2_rn(a, b);
    return *reinterpret_cast<uint32_t*>(&h);
}

// ---------------------------------------------------------------------------
// One-shot fp16 pre-conversion of x, Wqk, Wv, Wo
// ---------------------------------------------------------------------------
#define N4_X   3145728
#define N4_QK  294912
#define N4_V   147456
#define N4_O   147456
#define N4_ALL (N4_X + N4_QK + N4_V + N4_O)

__global__ void cvt_all(const float4* __restrict__ x,
                        const float4* __restrict__ wqk,
                        const float4* __restrict__ wv,
                        const float4* __restrict__ wo) {
    int i = blockIdx.x * 256 + threadIdx.x;
    const float4* src;
    __half2* dst;
    int j;
    if (i < N4_X) { src = x; dst = (__half2*)g_xt; j = i; }
    else if (i < N4_X + N4_QK) { src = wqk; dst = (__half2*)g_wqkt; j = i - N4_X; }
    else if (i < N4_X + N4_QK + N4_V) { src = wv; dst = (__half2*)g_wvt; j = i - N4_X - N4_QK; }
    else { src = wo; dst = (__half2*)g_wot; j = i - N4_X - N4_QK - N4_V; }
    float4 v = src[j];
    dst[2 * j]     = __floats2half2_rn(v.x, v.y);
    dst[2 * j + 1] = __floats2half2_rn(v.z, v.w);
}

// ---------------------------------------------------------------------------
// fp16 tensor-core GEMM, BK=64, 3-stage cp.async, ldmatrix fragments.
// Block 128x128, 256 threads = 8 warps (2x4), warp tile 64x32, 2 CTAs/SM.
// MODE 0: A = g_xt; blocks x<12 -> QK proj, x>=12 -> V proj; smem-staged
//         coalesced epilogue (Q scaled by log2e).
// MODE 2: A = g_O2 (dense), W = g_wot, result -> out (fp32 direct).
// ---------------------------------------------------------------------------
#define BM 128
#define BN 128
#define NT2 12                               // 768 / 64
#define SSTH 72                              // padded row stride (halves)
#define STG_BYTES ((BM + BN) * SSTH * 2)     // 36864
#define GEMM_SMEM (3 * STG_BYTES)            // 110592
#define EPST 136                             // epilogue smem row stride (halves)

template <int MODE>
__global__ void __launch_bounds__(256, 2)
mma_gemm(const float* __restrict__ b0, const float* __restrict__ b1,
         float* __restrict__ out) {
    extern __shared__ uint32_t dsm[];
    const uint32_t smb = smem_u32(dsm);
    const int tid = threadIdx.x;
    const int lane = tid & 31;
    const int wid = tid >> 5;
    const int g = lane >> 2;
    const int t = lane & 3;
    const int wr = wid >> 2;      // 0..1
    const int wc = wid & 3;       // 0..3
    const int m0 = blockIdx.y * BM;

    const __half* Abase = (MODE == 0) ? g_xt : g_O2;
    const __half* W;
    const float* bias;
    int ncol0;
    int isV = 0;
    if (MODE == 0) {
        if (blockIdx.x < 12) { W = g_wqkt; bias = b0; ncol0 = blockIdx.x * BN; }
        else { W = g_wvt; bias = b1; ncol0 = (blockIdx.x - 12) * BN; isV = 1; }
    } else {
        W = g_wot; bias = b0; ncol0 = blockIdx.x * BN;
    }

    float acc[4][4][4];
#pragma unroll
    for (int mi = 0; mi < 4; mi++)
#pragma unroll
        for (int ni = 0; ni < 4; ni++)
#pragma unroll
            for (int r = 0; r < 4; r++) acc[mi][ni][r] = 0.0f;

    const uint32_t aoffA = lda_off_h(lane, SSTH);
    const uint32_t boffB = ldb_off_h(lane, SSTH);

#define ISSUE_TILE(kt, st)                                                     \
    do {                                                                       \
        _Pragma("unroll") for (int i = 0; i < 4; i++) {   /* A: 128x64h */     \
            int c = tid + i * 256;                                             \
            int r = c >> 3, q = (c & 7) * 8;                                   \
            uint32_t dA = smb + (st) * STG_BYTES + (uint32_t)((r * SSTH + q) * 2);\
            cpa16(dA, Abase + (size_t)(m0 + r) * DMODEL + (kt) * 64 + q);      \
            cpa16(dA + BM * SSTH * 2,                                          \
                  W + (size_t)(ncol0 + r) * DMODEL + (kt) * 64 + q);           \
        }                                                                      \
    } while (0)

    ISSUE_TILE(0, 0); CP_COMMIT();
    ISSUE_TILE(1, 1); CP_COMMIT();

    for (int kt = 0; kt < NT2; kt++) {
        if (kt < NT2 - 1) { CP_WAIT1(); } else { CP_WAIT0(); }
        __syncthreads();              // tile kt ready; stage (kt+2)%3 free
        if (kt + 2 < NT2) { ISSUE_TILE(kt + 2, (kt + 2) % 3); CP_COMMIT(); }

        const uint32_t stB = smb + (kt % 3) * STG_BYTES;
        const uint32_t aA = stB + (uint32_t)(wr * 64 * SSTH * 2) + aoffA;
        const uint32_t aB = stB + (uint32_t)((BM + wc * 32) * SSTH * 2) + boffB;

#pragma unroll
        for (int ks = 0; ks < 4; ks++) {
            const uint32_t kb = ks * 32;          // 16 halves
            uint32_t bf[4][2];
            {
                uint32_t r[4];
                ldm_x4(r, aB + kb);                       // n 0..15
                bf[0][0] = r[0]; bf[0][1] = r[1];
                bf[1][0] = r[2]; bf[1][1] = r[3];
                ldm_x4(r, aB + 16 * SSTH * 2 + kb);       // n 16..31
                bf[2][0] = r[0]; bf[2][1] = r[1];
                bf[3][0] = r[2]; bf[3][1] = r[3];
            }
#pragma unroll
            for (int mi = 0; mi < 4; mi++) {
                uint32_t af[4];
                ldm_x4(af, aA + (uint32_t)(mi * 16 * SSTH * 2) + kb);
#pragma unroll
                for (int ni = 0; ni < 4; ni++)
                    MMA_F16(acc[mi][ni], af, bf[ni]);
            }
        }
    }
#undef ISSUE_TILE

    // ---- epilogue ----
    if (MODE == 2) {
#pragma unroll
        for (int ni = 0; ni < 4; ni++) {
            int gc = ncol0 + wc * 32 + ni * 8 + 2 * t;
            float bb0 = bias[gc], bb1 = bias[gc + 1];
#pragma unroll
            for (int mi = 0; mi < 4; mi++) {
                int r_lo = m0 + wr * 64 + mi * 16 + g;
                out[(size_t)r_lo * DMODEL + gc]           = acc[mi][ni][0] + bb0;
                out[(size_t)r_lo * DMODEL + gc + 1]       = acc[mi][ni][1] + bb1;
                out[(size_t)(r_lo + 8) * DMODEL + gc]     = acc[mi][ni][2] + bb0;
                out[(size_t)(r_lo + 8) * DMODEL + gc + 1] = acc[mi][ni][3] + bb1;
            }
        }
    } else {
        __syncthreads();                 // stage buffers free for reuse
        __half* ep = (__half*)dsm;       // [128][EPST]
        // Q columns (even parity in QK blocks) get the log2e pre-scale
        const float qs = isV ? 1.0f : LOG2E;
#pragma unroll
        for (int ni = 0; ni < 4; ni++) {
            int lc = wc * 32 + ni * 8 + 2 * t;
            int gc = ncol0 + lc;
            float bb0 = bias[gc], bb1 = bias[gc + 1];
#pragma unroll
            for (int mi = 0; mi < 4; mi++) {
                int rl = wr * 64 + mi * 16 + g;
                // even local col = Q element (scale), odd = K (no scale)
                *(__half2*)&ep[rl * EPST + lc] = __floats2half2_rn(
                    (acc[mi][ni][0] + bb0) * qs, acc[mi][ni][1] + bb1);
                *(__half2*)&ep[(rl + 8) * EPST + lc] = __floats2half2_rn(
                    (acc[mi][ni][2] + bb0) * qs, acc[mi][ni][3] + bb1);
            }
        }
        __syncthreads();

        if (!isV) {
            // QK block: one head h0; word w of a row = (Q[w], K[w])
            const int h0 = ncol0 >> 7;
#pragma unroll
            for (int i = 0; i < 4; i++) {
                int c = tid + i * 256;               // 0..1023
                int row = c >> 3, e0 = (c & 7) * 8;
                int m = m0 + row, bb = m >> 10, nn = m & 1023;
                const uint32_t* src = (const uint32_t*)&ep[row * EPST] + e0;
                uint32_t u[8];
#pragma unroll
                for (int j = 0; j < 8; j++) u[j] = src[j];
                uint4 qv, kv;
                qv.x = __byte_perm(u[0], u[1], 0x5410);
                qv.y = __byte_perm(u[2], u[3], 0x5410);
                qv.z = __byte_perm(u[4], u[5], 0x5410);
                qv.w = __byte_perm(u[6], u[7], 0x5410);
                kv.x = __byte_perm(u[0], u[1], 0x7632);
                kv.y = __byte_perm(u[2], u[3], 0x7632);
                kv.z = __byte_perm(u[4], u[5], 0x7632);
                kv.w = __byte_perm(u[6], u[7], 0x7632);
                size_t base = ((size_t)(bb * NHEAD + h0) * SEQ + nn) * EDIM + e0;
                *(uint4*)(g_Q + base) = qv;
                *(uint4*)(g_K + base) = kv;
            }
        } else {
            // V block: two dense head tiles
            const int hA = ncol0 >> 6;
#pragma unroll
            for (int i = 0; i < 8; i++) {
                int c = tid + i * 256;               // 0..2047
                int row = c >> 4, ch = c & 15;
                int m = m0 + row, bb = m >> 10, nn = m & 1023;
                uint4 v = *(const uint4*)&ep[row * EPST + ch * 8];
                int h = hA + (ch >> 3), e0 = (ch * 8) & 63;
                *(uint4*)(g_V + ((size_t)(bb * NHEAD + h) * SEQ + nn) * EDIM + e0) = v;
            }
        }
    }
}

// ---------------------------------------------------------------------------
// fp16 flash attention, 128-query tiles, 256 threads (8 warps), 2 CTAs/SM.
// P in registers; 3-stage cp.async K/V; exp via ex2 (Q pre-scaled by log2e).
// Output written DENSE into g_O2 [M x 768].
// Smem: K[3][64][72] + V[3][64][72]  (halves)
// ---------------------------------------------------------------------------
#define KSTH 72
#define KVH (2 * 64 * KSTH)                  // halves per stage = 9216
#define AT_SMEM (3 * KVH * 2)                // 55296 B
#define NKT (SEQ / 64)                       // 16 key tiles

__global__ void __launch_bounds__(256, 2) attn_tc() {
    extern __shared__ __half smh[];
    const uint32_t smb = smem_u32(smh);

    const int tid = threadIdx.x;
    const int lane = tid & 31;
    const int wid = tid >> 5;
    const int g = lane >> 2;
    const int t = lane & 3;
    const int r0 = wid * 16;          // warp's query-row base (0..112)
    const int qt = blockIdx.x;        // 0..7
    const int h  = blockIdx.y;
    const int b  = blockIdx.z;
    const int bh = b * NHEAD + h;

    const uint32_t* Qw =
        (const uint32_t*)(g_Q + ((size_t)bh * SEQ + qt * 128) * EDIM);
    const __half* Kg0 = g_K + (size_t)bh * SEQ * EDIM;
    const __half* Vg0 = g_V + (size_t)bh * SEQ * EDIM;

    // Q fragments (fp16 pairs), 16 regs
    uint32_t qf[4][4];
#pragma unroll
    for (int ks = 0; ks < 4; ks++) {
        qf[ks][0] = Qw[(r0 + g) * 32 + ks * 8 + t];
        qf[ks][1] = Qw[(r0 + g + 8) * 32 + ks * 8 + t];
        qf[ks][2] = Qw[(r0 + g) * 32 + ks * 8 + t + 4];
        qf[ks][3] = Qw[(r0 + g + 8) * 32 + ks * 8 + t + 4];
    }

    const uint32_t boffK = ldb_off_h(lane, KSTH);
    const uint32_t aoffV = lda_off_h(lane, KSTH);

#define ISSUE_KV(kt, st)                                                       \
    do {                                                                       \
        const __half* Kg = Kg0 + (kt) * 64 * EDIM;                             \
        const __half* Vg = Vg0 + (kt) * 64 * EDIM;                             \
        _Pragma("unroll") for (int i = 0; i < 2; i++) {                        \
            int c = tid + i * 256;                                             \
            int row = c >> 3, q = (c & 7) * 8;                                 \
            cpa16(smb + (uint32_t)(((st) * KVH + row * KSTH + q) * 2),         \
                  Kg + row * EDIM + q);                                        \
            cpa16(smb + (uint32_t)(((st) * KVH + 64 * KSTH + row * KSTH + q) * 2),\
                  Vg + row * EDIM + q);                                        \
        }                                                                      \
    } while (0)

    ISSUE_KV(0, 0); CP_COMMIT();
    ISSUE_KV(1, 1); CP_COMMIT();

    float o[8][4];
#pragma unroll
    for (int ni = 0; ni < 8; ni++)
#pragma unroll
        for (int r = 0; r < 4; r++) o[ni][r] = 0.0f;
    float mrow0 = -1e30f, mrow1 = -1e30f, l0 = 0.0f, l1 = 0.0f;

    for (int kt = 0; kt < NKT; kt++) {
        if (kt < NKT - 1) { CP_WAIT1(); } else { CP_WAIT0(); }
        __syncthreads();             // tile kt visible; stage (kt+2)%3 free
        if (kt + 2 < NKT) { ISSUE_KV(kt + 2, (kt + 2) % 3); CP_COMMIT(); }
        const uint32_t ksb = smb + (uint32_t)((kt % 3) * KVH * 2);
        const uint32_t vsb = ksb + (uint32_t)(64 * KSTH * 2);

        // ---- S = Q @ K^T  (S is in log2 domain: Q pre-scaled) ----
        float s[8][4];
#pragma unroll
        for (int ni = 0; ni < 8; ni++)
#pragma unroll
            for (int r = 0; r < 4; r++) s[ni][r] = 0.0f;
#pragma unroll
        for (int ks = 0; ks < 4; ks++) {
            const uint32_t kb = ks * 32;
#pragma unroll
            for (int j = 0; j < 4; j++) {
                uint32_t r[4];
                ldm_x4(r, ksb + boffK + (uint32_t)(j * 16 * KSTH * 2) + kb);
                uint32_t bf0[2] = {r[0], r[1]};
                uint32_t bf1[2] = {r[2], r[3]};
                MMA_F16(s[2 * j],     qf[ks], bf0);
                MMA_F16(s[2 * j + 1], qf[ks], bf1);
            }
        }

        // ---- online softmax (2^x domain); P packed into A-fragments ----
        float mx0 = -1e30f, mx1 = -1e30f;
#pragma unroll
        for (int ni = 0; ni < 8; ni++) {
            mx0 = fmaxf(mx0, fmaxf(s[ni][0], s[ni][1]));
            mx1 = fmaxf(mx1, fmaxf(s[ni][2], s[ni][3]));
        }
        mx0 = fmaxf(mx0, __shfl_xor_sync(0xffffffffu, mx0, 1));
        mx0 = fmaxf(mx0, __shfl_xor_sync(0xffffffffu, mx0, 2));
        mx1 = fmaxf(mx1, __shfl_xor_sync(0xffffffffu, mx1, 1));
        mx1 = fmaxf(mx1, __shfl_xor_sync(0xffffffffu, mx1, 2));
        float mn0 = fmaxf(mrow0, mx0), mn1 = fmaxf(mrow1, mx1);
        float al0 = ex2(mrow0 - mn0), al1 = ex2(mrow1 - mn1);
        mrow0 = mn0; mrow1 = mn1;
        float sum0 = 0.0f, sum1 = 0.0f;
        uint32_t pf[4][4];
#pragma unroll
        for (int ni = 0; ni < 8; ni++) {
            float p0 = ex2(s[ni][0] - mn0);
            float p1 = ex2(s[ni][1] - mn0);
            float p2 = ex2(s[ni][2] - mn1);
            float p3 = ex2(s[ni][3] - mn1);
            sum0 += p0 + p1;
            sum1 += p2 + p3;
            o[ni][0] *= al0; o[ni][1] *= al0;
            o[ni][2] *= al1; o[ni][3] *= al1;
            int ks = ni >> 1;
            uint32_t lo = packh2(p0, p1);
            uint32_t hi = packh2(p2, p3);
            if (ni & 1) { pf[ks][2] = lo; pf[ks][3] = hi; }
            else        { pf[ks][0] = lo; pf[ks][1] = hi; }
        }
        sum0 += __shfl_xor_sync(0xffffffffu, sum0, 1);
        sum0 += __shfl_xor_sync(0xffffffffu, sum0, 2);
        sum1 += __shfl_xor_sync(0xffffffffu, sum1, 1);
        sum1 += __shfl_xor_sync(0xffffffffu, sum1, 2);
        l0 = l0 * al0 + sum0;
        l1 = l1 * al1 + sum1;

        // ---- O += P @ V (P in registers, V via ldmatrix.trans) ----
#pragma unroll
        for (int ks = 0; ks < 4; ks++) {
#pragma unroll
            for (int j = 0; j < 4; j++) {
                uint32_t r[4];
                ldm_x4_t(r, vsb + aoffV +
                            (uint32_t)((ks * 16 * KSTH + j * 16) * 2));
                uint32_t bf0[2] = {r[0], r[1]};
                uint32_t bf1[2] = {r[2], r[3]};
                MMA_F16(o[2 * j],     pf[ks], bf0);
                MMA_F16(o[2 * j + 1], pf[ks], bf1);
            }
        }
    }
#undef ISSUE_KV

    // ---- finalize: write DENSE rows of g_O2 [M x 768] ----
    float inv0 = 1.0f / (l0 * SOFTMAX_DIV);
    float inv1 = 1.0f / (l1 * SOFTMAX_DIV);

    __half* Ob = g_O2 + (size_t)(b * SEQ + qt * 128) * DMODEL + h * EDIM;
#pragma unroll
    for (int ni = 0; ni < 8; ni++) {
        *(__half2*)&Ob[(size_t)(r0 + g) * DMODEL + ni * 8 + 2 * t] =
            __floats2half2_rn(o[ni][0] * inv0, o[ni][1] * inv0);
        *(__half2*)&Ob[(size_t)(r0 + g + 8) * DMODEL + ni * 8 + 2 * t] =
            __floats2half2_rn(o[ni][2] * inv1, o[ni][3] * inv1);
    }
}

// ---------------------------------------------------------------------------
// kernel_launch
// ---------------------------------------------------------------------------
extern "C" void kernel_launch(void* const* d_in, const int* in_sizes, int n_in,
                              void* d_out, int out_size) {
    const float* x      = (const float*)d_in[0];
    const float* Wqk_w  = (const float*)d_in[1];
    const float* Wqk_b  = (const float*)d_in[2];
    const float* Wv_w   = (const float*)d_in[3];
    const float* Wv_b   = (const float*)d_in[4];
    const float* Wo_w   = (const float*)d_in[5];
    const float* Wo_b   = (const float*)d_in[6];
    float* out = (float*)d_out;

    (void)in_sizes; (void)n_in; (void)out_size;

    cudaFuncSetAttribute(mma_gemm<0>, cudaFuncAttributeMaxDynamicSharedMemorySize, GEMM_SMEM);
    cudaFuncSetAttribute(mma_gemm<2>, cudaFuncAttributeMaxDynamicSharedMemorySize, GEMM_SMEM);
    cudaFuncSetAttribute(attn_tc, cudaFuncAttributeMaxDynamicSharedMemorySize, AT_SMEM);

    // 0) pre-round x / weights to fp16
    cvt_all<<<N4_ALL / 256, 256>>>((const float4*)x, (const float4*)Wqk_w,
                                   (const float4*)Wv_w, (const float4*)Wo_w);
    // 1) fused QKV projections -> g_Q (log2e-scaled), g_K, g_V
    mma_gemm<0><<<dim3(18, 128), 256, GEMM_SMEM>>>(Wqk_b, Wv_b, nullptr);
    // 2) attention -> g_O2 (dense concat)
    attn_tc<<<dim3(SEQ / 128, NHEAD, BSZ), 256, AT_SMEM>>>();
    // 3) output projection -> d_out
    mma_gemm<2><<<dim3(6, 128), 256, GEMM_SMEM>>>(Wo_b, nullptr, out);
}

// round 15
// speedup vs baseline: 1.0030x; 1.0030x over previous
#include <cuda_runtime.h>
#include <cuda_fp16.h>
#include <cstdint>
#include <math.h>

// ---------------------------------------------------------------------------
// Problem constants
// ---------------------------------------------------------------------------
#define BSZ 16
#define SEQ 1024
#define DMODEL 768
#define NHEAD 12
#define EDIM 64
#define SOFTMAX_DIV 27.712812921102035f
#define LOG2E 1.4426950408889634f

#define BHNE (BSZ * NHEAD * SEQ * EDIM)
__device__ __half g_Q[BHNE];                    // pre-scaled by log2(e)
__device__ __half g_K[BHNE];
__device__ __half g_V[BHNE];
__device__ __half g_O2[BSZ * SEQ * DMODEL];     // dense concat matrix

// pre-converted fp16 operands
__device__ __half g_xt[BSZ * SEQ * DMODEL];
__device__ __half g_wqkt[2 * DMODEL * DMODEL];
__device__ __half g_wvt[DMODEL * DMODEL];
__device__ __half g_wot[DMODEL * DMODEL];

// ---------------------------------------------------------------------------
// helpers (plain sm_80+ PTX only)
// ---------------------------------------------------------------------------
__device__ __forceinline__ uint32_t smem_u32(const void* p) {
    uint32_t a;
    asm("{ .reg .u64 t; cvta.to.shared.u64 t, %1; cvt.u32.u64 %0, t; }"
        : "=r"(a) : "l"(p));
    return a;
}
__device__ __forceinline__ void cpa16(uint32_t dst, const void* src) {
    asm volatile("cp.async.cg.shared.global [%0], [%1], 16;"
                 :: "r"(dst), "l"(src));
}
#define CP_COMMIT() asm volatile("cp.async.commit_group;" ::: "memory")
#define CP_WAIT0()  asm volatile("cp.async.wait_group 0;" ::: "memory")
#define CP_WAIT1()  asm volatile("cp.async.wait_group 1;" ::: "memory")

__device__ __forceinline__ float ex2(float x) {
    float y;
    asm("ex2.approx.f32 %0, %1;" : "=f"(y) : "f"(x));
    return y;
}

#define MMA_F16(acc, af, bf)                                                   \
    asm volatile(                                                              \
        "mma.sync.aligned.m16n8k16.row.col.f32.f16.f16.f32 "                   \
        "{%0,%1,%2,%3}, {%4,%5,%6,%7}, {%8,%9}, {%0,%1,%2,%3};"                \
        : "+f"((acc)[0]), "+f"((acc)[1]), "+f"((acc)[2]), "+f"((acc)[3])       \
        : "r"((af)[0]), "r"((af)[1]), "r"((af)[2]), "r"((af)[3]),              \
          "r"((bf)[0]), "r"((bf)[1]))

__device__ __forceinline__ void ldm_x4(uint32_t* r, uint32_t addr) {
    asm volatile(
        "ldmatrix.sync.aligned.m8n8.x4.shared.b16 {%0,%1,%2,%3}, [%4];"
        : "=r"(r[0]), "=r"(r[1]), "=r"(r[2]), "=r"(r[3]) : "r"(addr));
}
__device__ __forceinline__ void ldm_x4_t(uint32_t* r, uint32_t addr) {
    asm volatile(
        "ldmatrix.sync.aligned.m8n8.x4.trans.shared.b16 {%0,%1,%2,%3}, [%4];"
        : "=r"(r[0]), "=r"(r[1]), "=r"(r[2]), "=r"(r[3]) : "r"(addr));
}
// A-style x4: matrices (R,k0),(R+8,k0),(R,k8),(R+8,k8)  (ST in halves)
__device__ __forceinline__ uint32_t lda_off_h(int lane, int ST) {
    int row = (lane & 7) + ((lane >> 3) & 1) * 8;
    int koff = ((lane >> 4) & 1) * 8;
    return (uint32_t)((row * ST + koff) * 2);
}
// B-style x4: matrices (N,k0),(N,k8),(N+8,k0),(N+8,k8)
__device__ __forceinline__ uint32_t ldb_off_h(int lane, int ST) {
    int row = (lane & 7) + ((lane >> 4) & 1) * 8;
    int koff = ((lane >> 3) & 1) * 8;
    return (uint32_t)((row * ST + koff) * 2);
}
__device__ __forceinline__ uint32_t packh2(float a, float b) {
    __half2 h = __floats2half2_rn(a, b);
    return *reinterpret_cast<uint32_t*>(&h);
}

// ---------------------------------------------------------------------------
// One-shot fp16 pre-conversion of x, Wqk, Wv, Wo
// ---------------------------------------------------------------------------
#define N4_X   3145728
#define N4_QK  294912
#define N4_V   147456
#define N4_O   147456
#define N4_ALL (N4_X + N4_QK + N4_V + N4_O)

__global__ void cvt_all(const float4* __restrict__ x,
                        const float4* __restrict__ wqk,
                        const float4* __restrict__ wv,
                        const float4* __restrict__ wo) {
    int i = blockIdx.x * 256 + threadIdx.x;
    const float4* src;
    __half2* dst;
    int j;
    if (i < N4_X) { src = x; dst = (__half2*)g_xt; j = i; }
    else if (i < N4_X + N4_QK) { src = wqk; dst = (__half2*)g_wqkt; j = i - N4_X; }
    else if (i < N4_X + N4_QK + N4_V) { src = wv; dst = (__half2*)g_wvt; j = i - N4_X - N4_QK; }
    else { src = wo; dst = (__half2*)g_wot; j = i - N4_X - N4_QK - N4_V; }
    float4 v = src[j];
    dst[2 * j]     = __floats2half2_rn(v.x, v.y);
    dst[2 * j + 1] = __floats2half2_rn(v.z, v.w);
}

// ---------------------------------------------------------------------------
// fp16 tensor-core GEMM, BK=64, 3-stage cp.async, warp tile 64x64.
// Block 128x128, 128 threads = 4 warps (2x2), 2 CTAs/SM.
// MODE 0: A = g_xt; blocks x<12 -> QK proj, x>=12 -> V proj; smem-staged
//         coalesced epilogue (Q scaled by log2e).
// MODE 2: A = g_O2 (dense), W = g_wot, result -> out (fp32 direct).
// ---------------------------------------------------------------------------
#define BM 128
#define BN 128
#define NT2 12                               // 768 / 64
#define SSTH 72                              // padded row stride (halves)
#define STG_BYTES ((BM + BN) * SSTH * 2)     // 36864
#define GEMM_SMEM (3 * STG_BYTES)            // 110592
#define EPST 136                             // epilogue smem row stride (halves)

template <int MODE>
__global__ void __launch_bounds__(128, 2)
mma_gemm(const float* __restrict__ b0, const float* __restrict__ b1,
         float* __restrict__ out) {
    extern __shared__ uint32_t dsm[];
    const uint32_t smb = smem_u32(dsm);
    const int tid = threadIdx.x;
    const int lane = tid & 31;
    const int wid = tid >> 5;
    const int g = lane >> 2;
    const int t = lane & 3;
    const int wr = wid >> 1;      // 0..1 (64-row band)
    const int wc = wid & 1;       // 0..1 (64-col band)
    const int m0 = blockIdx.y * BM;

    const __half* Abase = (MODE == 0) ? g_xt : g_O2;
    const __half* W;
    const float* bias;
    int ncol0;
    int isV = 0;
    if (MODE == 0) {
        if (blockIdx.x < 12) { W = g_wqkt; bias = b0; ncol0 = blockIdx.x * BN; }
        else { W = g_wvt; bias = b1; ncol0 = (blockIdx.x - 12) * BN; isV = 1; }
    } else {
        W = g_wot; bias = b0; ncol0 = blockIdx.x * BN;
    }

    float acc[4][8][4];
#pragma unroll
    for (int mi = 0; mi < 4; mi++)
#pragma unroll
        for (int ni = 0; ni < 8; ni++)
#pragma unroll
            for (int r = 0; r < 4; r++) acc[mi][ni][r] = 0.0f;

    const uint32_t aoffA = lda_off_h(lane, SSTH);
    const uint32_t boffB = ldb_off_h(lane, SSTH);

#define ISSUE_TILE(kt, st)                                                     \
    do {                                                                       \
        _Pragma("unroll") for (int i = 0; i < 8; i++) {   /* A: 128x64h */     \
            int c = tid + i * 128;                                             \
            int r = c >> 3, q = (c & 7) * 8;                                   \
            uint32_t dA = smb + (st) * STG_BYTES + (uint32_t)((r * SSTH + q) * 2);\
            cpa16(dA, Abase + (size_t)(m0 + r) * DMODEL + (kt) * 64 + q);      \
            cpa16(dA + BM * SSTH * 2,                                          \
                  W + (size_t)(ncol0 + r) * DMODEL + (kt) * 64 + q);           \
        }                                                                      \
    } while (0)

    ISSUE_TILE(0, 0); CP_COMMIT();
    ISSUE_TILE(1, 1); CP_COMMIT();

    for (int kt = 0; kt < NT2; kt++) {
        if (kt < NT2 - 1) { CP_WAIT1(); } else { CP_WAIT0(); }
        __syncthreads();              // tile kt ready; stage (kt+2)%3 free
        if (kt + 2 < NT2) { ISSUE_TILE(kt + 2, (kt + 2) % 3); CP_COMMIT(); }

        const uint32_t stB = smb + (kt % 3) * STG_BYTES;
        const uint32_t aA = stB + (uint32_t)(wr * 64 * SSTH * 2) + aoffA;
        const uint32_t aB = stB + (uint32_t)((BM + wc * 64) * SSTH * 2) + boffB;

#pragma unroll
        for (int ks = 0; ks < 4; ks++) {
            const uint32_t kb = ks * 32;          // 16 halves
            uint32_t bf[8][2];
#pragma unroll
            for (int j = 0; j < 4; j++) {
                uint32_t r[4];
                ldm_x4(r, aB + (uint32_t)(j * 16 * SSTH * 2) + kb);
                bf[2 * j][0] = r[0];     bf[2 * j][1] = r[1];
                bf[2 * j + 1][0] = r[2]; bf[2 * j + 1][1] = r[3];
            }
#pragma unroll
            for (int mi = 0; mi < 4; mi++) {
                uint32_t af[4];
                ldm_x4(af, aA + (uint32_t)(mi * 16 * SSTH * 2) + kb);
#pragma unroll
                for (int ni = 0; ni < 8; ni++)
                    MMA_F16(acc[mi][ni], af, bf[ni]);
            }
        }
    }
#undef ISSUE_TILE

    // ---- epilogue ----
    if (MODE == 2) {
#pragma unroll
        for (int ni = 0; ni < 8; ni++) {
            int gc = ncol0 + wc * 64 + ni * 8 + 2 * t;
            float bb0 = bias[gc], bb1 = bias[gc + 1];
#pragma unroll
            for (int mi = 0; mi < 4; mi++) {
                int r_lo = m0 + wr * 64 + mi * 16 + g;
                out[(size_t)r_lo * DMODEL + gc]           = acc[mi][ni][0] + bb0;
                out[(size_t)r_lo * DMODEL + gc + 1]       = acc[mi][ni][1] + bb1;
                out[(size_t)(r_lo + 8) * DMODEL + gc]     = acc[mi][ni][2] + bb0;
                out[(size_t)(r_lo + 8) * DMODEL + gc + 1] = acc[mi][ni][3] + bb1;
            }
        }
    } else {
        __syncthreads();                 // stage buffers free for reuse
        __half* ep = (__half*)dsm;       // [128][EPST]
        const float qs = isV ? 1.0f : LOG2E;
#pragma unroll
        for (int ni = 0; ni < 8; ni++) {
            int lc = wc * 64 + ni * 8 + 2 * t;
            int gc = ncol0 + lc;
            float bb0 = bias[gc], bb1 = bias[gc + 1];
#pragma unroll
            for (int mi = 0; mi < 4; mi++) {
                int rl = wr * 64 + mi * 16 + g;
                *(__half2*)&ep[rl * EPST + lc] = __floats2half2_rn(
                    (acc[mi][ni][0] + bb0) * qs, acc[mi][ni][1] + bb1);
                *(__half2*)&ep[(rl + 8) * EPST + lc] = __floats2half2_rn(
                    (acc[mi][ni][2] + bb0) * qs, acc[mi][ni][3] + bb1);
            }
        }
        __syncthreads();

        if (!isV) {
            // QK block: one head h0; word w of a row = (Q[w], K[w])
            const int h0 = ncol0 >> 7;
#pragma unroll
            for (int i = 0; i < 8; i++) {
                int c = tid + i * 128;               // 0..1023
                int row = c >> 3, e0 = (c & 7) * 8;
                int m = m0 + row, bb = m >> 10, nn = m & 1023;
                const uint32_t* src = (const uint32_t*)&ep[row * EPST] + e0;
                uint32_t u[8];
#pragma unroll
                for (int j = 0; j < 8; j++) u[j] = src[j];
                uint4 qv, kv;
                qv.x = __byte_perm(u[0], u[1], 0x5410);
                qv.y = __byte_perm(u[2], u[3], 0x5410);
                qv.z = __byte_perm(u[4], u[5], 0x5410);
                qv.w = __byte_perm(u[6], u[7], 0x5410);
                kv.x = __byte_perm(u[0], u[1], 0x7632);
                kv.y = __byte_perm(u[2], u[3], 0x7632);
                kv.z = __byte_perm(u[4], u[5], 0x7632);
                kv.w = __byte_perm(u[6], u[7], 0x7632);
                size_t base = ((size_t)(bb * NHEAD + h0) * SEQ + nn) * EDIM + e0;
                *(uint4*)(g_Q + base) = qv;
                *(uint4*)(g_K + base) = kv;
            }
        } else {
            // V block: two dense head tiles
            const int hA = ncol0 >> 6;
#pragma unroll
            for (int i = 0; i < 16; i++) {
                int c = tid + i * 128;               // 0..2047
                int row = c >> 4, ch = c & 15;
                int m = m0 + row, bb = m >> 10, nn = m & 1023;
                uint4 v = *(const uint4*)&ep[row * EPST + ch * 8];
                int h = hA + (ch >> 3), e0 = (ch * 8) & 63;
                *(uint4*)(g_V + ((size_t)(bb * NHEAD + h) * SEQ + nn) * EDIM + e0) = v;
            }
        }
    }
}

// ---------------------------------------------------------------------------
// fp16 flash attention, 128-query tiles, 256 threads (8 warps), 2 CTAs/SM.
// P in registers; 3-stage cp.async K/V; exp via ex2 (Q pre-scaled by log2e).
// Output written DENSE into g_O2 [M x 768].  (unchanged from R14)
// ---------------------------------------------------------------------------
#define KSTH 72
#define KVH (2 * 64 * KSTH)                  // halves per stage = 9216
#define AT_SMEM (3 * KVH * 2)                // 55296 B
#define NKT (SEQ / 64)                       // 16 key tiles

__global__ void __launch_bounds__(256, 2) attn_tc() {
    extern __shared__ __half smh[];
    const uint32_t smb = smem_u32(smh);

    const int tid = threadIdx.x;
    const int lane = tid & 31;
    const int wid = tid >> 5;
    const int g = lane >> 2;
    const int t = lane & 3;
    const int r0 = wid * 16;          // warp's query-row base (0..112)
    const int qt = blockIdx.x;        // 0..7
    const int h  = blockIdx.y;
    const int b  = blockIdx.z;
    const int bh = b * NHEAD + h;

    const uint32_t* Qw =
        (const uint32_t*)(g_Q + ((size_t)bh * SEQ + qt * 128) * EDIM);
    const __half* Kg0 = g_K + (size_t)bh * SEQ * EDIM;
    const __half* Vg0 = g_V + (size_t)bh * SEQ * EDIM;

    // Q fragments (fp16 pairs), 16 regs
    uint32_t qf[4][4];
#pragma unroll
    for (int ks = 0; ks < 4; ks++) {
        qf[ks][0] = Qw[(r0 + g) * 32 + ks * 8 + t];
        qf[ks][1] = Qw[(r0 + g + 8) * 32 + ks * 8 + t];
        qf[ks][2] = Qw[(r0 + g) * 32 + ks * 8 + t + 4];
        qf[ks][3] = Qw[(r0 + g + 8) * 32 + ks * 8 + t + 4];
    }

    const uint32_t boffK = ldb_off_h(lane, KSTH);
    const uint32_t aoffV = lda_off_h(lane, KSTH);

#define ISSUE_KV(kt, st)                                                       \
    do {                                                                       \
        const __half* Kg = Kg0 + (kt) * 64 * EDIM;                             \
        const __half* Vg = Vg0 + (kt) * 64 * EDIM;                             \
        _Pragma("unroll") for (int i = 0; i < 2; i++) {                        \
            int c = tid + i * 256;                                             \
            int row = c >> 3, q = (c & 7) * 8;                                 \
            cpa16(smb + (uint32_t)(((st) * KVH + row * KSTH + q) * 2),         \
                  Kg + row * EDIM + q);                                        \
            cpa16(smb + (uint32_t)(((st) * KVH + 64 * KSTH + row * KSTH + q) * 2),\
                  Vg + row * EDIM + q);                                        \
        }                                                                      \
    } while (0)

    ISSUE_KV(0, 0); CP_COMMIT();
    ISSUE_KV(1, 1); CP_COMMIT();

    float o[8][4];
#pragma unroll
    for (int ni = 0; ni < 8; ni++)
#pragma unroll
        for (int r = 0; r < 4; r++) o[ni][r] = 0.0f;
    float mrow0 = -1e30f, mrow1 = -1e30f, l0 = 0.0f, l1 = 0.0f;

    for (int kt = 0; kt < NKT; kt++) {
        if (kt < NKT - 1) { CP_WAIT1(); } else { CP_WAIT0(); }
        __syncthreads();             // tile kt visible; stage (kt+2)%3 free
        if (kt + 2 < NKT) { ISSUE_KV(kt + 2, (kt + 2) % 3); CP_COMMIT(); }
        const uint32_t ksb = smb + (uint32_t)((kt % 3) * KVH * 2);
        const uint32_t vsb = ksb + (uint32_t)(64 * KSTH * 2);

        // ---- S = Q @ K^T  (log2 domain) ----
        float s[8][4];
#pragma unroll
        for (int ni = 0; ni < 8; ni++)
#pragma unroll
            for (int r = 0; r < 4; r++) s[ni][r] = 0.0f;
#pragma unroll
        for (int ks = 0; ks < 4; ks++) {
            const uint32_t kb = ks * 32;
#pragma unroll
            for (int j = 0; j < 4; j++) {
                uint32_t r[4];
                ldm_x4(r, ksb + boffK + (uint32_t)(j * 16 * KSTH * 2) + kb);
                uint32_t bf0[2] = {r[0], r[1]};
                uint32_t bf1[2] = {r[2], r[3]};
                MMA_F16(s[2 * j],     qf[ks], bf0);
                MMA_F16(s[2 * j + 1], qf[ks], bf1);
            }
        }

        // ---- online softmax (2^x domain); P packed into A-fragments ----
        float mx0 = -1e30f, mx1 = -1e30f;
#pragma unroll
        for (int ni = 0; ni < 8; ni++) {
            mx0 = fmaxf(mx0, fmaxf(s[ni][0], s[ni][1]));
            mx1 = fmaxf(mx1, fmaxf(s[ni][2], s[ni][3]));
        }
        mx0 = fmaxf(mx0, __shfl_xor_sync(0xffffffffu, mx0, 1));
        mx0 = fmaxf(mx0, __shfl_xor_sync(0xffffffffu, mx0, 2));
        mx1 = fmaxf(mx1, __shfl_xor_sync(0xffffffffu, mx1, 1));
        mx1 = fmaxf(mx1, __shfl_xor_sync(0xffffffffu, mx1, 2));
        float mn0 = fmaxf(mrow0, mx0), mn1 = fmaxf(mrow1, mx1);
        float al0 = ex2(mrow0 - mn0), al1 = ex2(mrow1 - mn1);
        mrow0 = mn0; mrow1 = mn1;
        float sum0 = 0.0f, sum1 = 0.0f;
        uint32_t pf[4][4];
#pragma unroll
        for (int ni = 0; ni < 8; ni++) {
            float p0 = ex2(s[ni][0] - mn0);
            float p1 = ex2(s[ni][1] - mn0);
            float p2 = ex2(s[ni][2] - mn1);
            float p3 = ex2(s[ni][3] - mn1);
            sum0 += p0 + p1;
            sum1 += p2 + p3;
            o[ni][0] *= al0; o[ni][1] *= al0;
            o[ni][2] *= al1; o[ni][3] *= al1;
            int ks = ni >> 1;
            uint32_t lo = packh2(p0, p1);
            uint32_t hi = packh2(p2, p3);
            if (ni & 1) { pf[ks][2] = lo; pf[ks][3] = hi; }
            else        { pf[ks][0] = lo; pf[ks][1] = hi; }
        }
        sum0 += __shfl_xor_sync(0xffffffffu, sum0, 1);
        sum0 += __shfl_xor_sync(0xffffffffu, sum0, 2);
        sum1 += __shfl_xor_sync(0xffffffffu, sum1, 1);
        sum1 += __shfl_xor_sync(0xffffffffu, sum1, 2);
        l0 = l0 * al0 + sum0;
        l1 = l1 * al1 + sum1;

        // ---- O += P @ V (P in registers, V via ldmatrix.trans) ----
#pragma unroll
        for (int ks = 0; ks < 4; ks++) {
#pragma unroll
            for (int j = 0; j < 4; j++) {
                uint32_t r[4];
                ldm_x4_t(r, vsb + aoffV +
                            (uint32_t)((ks * 16 * KSTH + j * 16) * 2));
                uint32_t bf0[2] = {r[0], r[1]};
                uint32_t bf1[2] = {r[2], r[3]};
                MMA_F16(o[2 * j],     pf[ks], bf0);
                MMA_F16(o[2 * j + 1], pf[ks], bf1);
            }
        }
    }
#undef ISSUE_KV

    // ---- finalize: write DENSE rows of g_O2 [M x 768] ----
    float inv0 = 1.0f / (l0 * SOFTMAX_DIV);
    float inv1 = 1.0f / (l1 * SOFTMAX_DIV);

    __half* Ob = g_O2 + (size_t)(b * SEQ + qt * 128) * DMODEL + h * EDIM;
#pragma unroll
    for (int ni = 0; ni < 8; ni++) {
        *(__half2*)&Ob[(size_t)(r0 + g) * DMODEL + ni * 8 + 2 * t] =
            __floats2half2_rn(o[ni][0] * inv0, o[ni][1] * inv0);
        *(__half2*)&Ob[(size_t)(r0 + g + 8) * DMODEL + ni * 8 + 2 * t] =
            __floats2half2_rn(o[ni][2] * inv1, o[ni][3] * inv1);
    }
}

// ---------------------------------------------------------------------------
// kernel_launch
// ---------------------------------------------------------------------------
extern "C" void kernel_launch(void* const* d_in, const int* in_sizes, int n_in,
                              void* d_out, int out_size) {
    const float* x      = (const float*)d_in[0];
    const float* Wqk_w  = (const float*)d_in[1];
    const float* Wqk_b  = (const float*)d_in[2];
    const float* Wv_w   = (const float*)d_in[3];
    const float* Wv_b   = (const float*)d_in[4];
    const float* Wo_w   = (const float*)d_in[5];
    const float* Wo_b   = (const float*)d_in[6];
    float* out = (float*)d_out;

    (void)in_sizes; (void)n_in; (void)out_size;

    cudaFuncSetAttribute(mma_gemm<0>, cudaFuncAttributeMaxDynamicSharedMemorySize, GEMM_SMEM);
    cudaFuncSetAttribute(mma_gemm<2>, cudaFuncAttributeMaxDynamicSharedMemorySize, GEMM_SMEM);
    cudaFuncSetAttribute(attn_tc, cudaFuncAttributeMaxDynamicSharedMemorySize, AT_SMEM);

    // 0) pre-round x / weights to fp16
    cvt_all<<<N4_ALL / 256, 256>>>((const float4*)x, (const float4*)Wqk_w,
                                   (const float4*)Wv_w, (const float4*)Wo_w);
    // 1) fused QKV projections -> g_Q (log2e-scaled), g_K, g_V
    mma_gemm<0><<<dim3(18, 128), 128, GEMM_SMEM>>>(Wqk_b, Wv_b, nullptr);
    // 2) attention -> g_O2 (dense concat)
    attn_tc<<<dim3(SEQ / 128, NHEAD, BSZ), 256, AT_SMEM>>>();
    // 3) output projection -> d_out
    mma_gemm<2><<<dim3(6, 128), 128, GEMM_SMEM>>>(Wo_b, nullptr, out);
}

// round 16
// speedup vs baseline: 1.0392x; 1.0361x over previous
#include <cuda_runtime.h>
#include <cuda_fp16.h>
#include <cstdint>
#include <math.h>

// ---------------------------------------------------------------------------
// Problem constants
// ---------------------------------------------------------------------------
#define BSZ 16
#define SEQ 1024
#define DMODEL 768
#define NHEAD 12
#define EDIM 64
#define SOFTMAX_DIV 27.712812921102035f
#define LOG2E 1.4426950408889634f

#define BHNE (BSZ * NHEAD * SEQ * EDIM)
__device__ __half g_Q[BHNE];                    // pre-scaled by log2(e)
__device__ __half g_K[BHNE];
__device__ __half g_V[BHNE];
__device__ __half g_O2[BSZ * SEQ * DMODEL];     // dense concat matrix

// pre-converted fp16 operands
__device__ __half g_xt[BSZ * SEQ * DMODEL];
__device__ __half g_wqkt[2 * DMODEL * DMODEL];
__device__ __half g_wvt[DMODEL * DMODEL];
__device__ __half g_wot[DMODEL * DMODEL];

// ---------------------------------------------------------------------------
// helpers (plain sm_80+ PTX only)
// ---------------------------------------------------------------------------
__device__ __forceinline__ uint32_t smem_u32(const void* p) {
    uint32_t a;
    asm("{ .reg .u64 t; cvta.to.shared.u64 t, %1; cvt.u32.u64 %0, t; }"
        : "=r"(a) : "l"(p));
    return a;
}
__device__ __forceinline__ void cpa16(uint32_t dst, const void* src) {
    asm volatile("cp.async.cg.shared.global [%0], [%1], 16;"
                 :: "r"(dst), "l"(src));
}
#define CP_COMMIT() asm volatile("cp.async.commit_group;" ::: "memory")
#define CP_WAIT0()  asm volatile("cp.async.wait_group 0;" ::: "memory")
#define CP_WAIT1()  asm volatile("cp.async.wait_group 1;" ::: "memory")

__device__ __forceinline__ float ex2(float x) {
    float y;
    asm("ex2.approx.f32 %0, %1;" : "=f"(y) : "f"(x));
    return y;
}

#define MMA_F16(acc, af, bf)                                                   \
    asm volatile(                                                              \
        "mma.sync.aligned.m16n8k16.row.col.f32.f16.f16.f32 "                   \
        "{%0,%1,%2,%3}, {%4,%5,%6,%7}, {%8,%9}, {%0,%1,%2,%3};"                \
        : "+f"((acc)[0]), "+f"((acc)[1]), "+f"((acc)[2]), "+f"((acc)[3])       \
        : "r"((af)[0]), "r"((af)[1]), "r"((af)[2]), "r"((af)[3]),              \
          "r"((bf)[0]), "r"((bf)[1]))

__device__ __forceinline__ void ldm_x4(uint32_t* r, uint32_t addr) {
    asm volatile(
        "ldmatrix.sync.aligned.m8n8.x4.shared.b16 {%0,%1,%2,%3}, [%4];"
        : "=r"(r[0]), "=r"(r[1]), "=r"(r[2]), "=r"(r[3]) : "r"(addr));
}
__device__ __forceinline__ void ldm_x4_t(uint32_t* r, uint32_t addr) {
    asm volatile(
        "ldmatrix.sync.aligned.m8n8.x4.trans.shared.b16 {%0,%1,%2,%3}, [%4];"
        : "=r"(r[0]), "=r"(r[1]), "=r"(r[2]), "=r"(r[3]) : "r"(addr));
}
// A-style x4: matrices (R,k0),(R+8,k0),(R,k8),(R+8,k8)  (ST in halves)
__device__ __forceinline__ uint32_t lda_off_h(int lane, int ST) {
    int row = (lane & 7) + ((lane >> 3) & 1) * 8;
    int koff = ((lane >> 4) & 1) * 8;
    return (uint32_t)((row * ST + koff) * 2);
}
// B-style x4: matrices (N,k0),(N,k8),(N+8,k0),(N+8,k8)
__device__ __forceinline__ uint32_t ldb_off_h(int lane, int ST) {
    int row = (lane & 7) + ((lane >> 4) & 1) * 8;
    int koff = ((lane >> 3) & 1) * 8;
    return (uint32_t)((row * ST + koff) * 2);
}
__device__ __forceinline__ uint32_t packh2(float a, float b) {
    __half2 h = __floats2half2_rn(a, b);
    return *reinterpret_cast<uint32_t*>(&h);
}

// ---------------------------------------------------------------------------
// One-shot fp16 pre-conversion of x, Wqk, Wv, Wo
// ---------------------------------------------------------------------------
#define N4_X   3145728
#define N4_QK  294912
#define N4_V   147456
#define N4_O   147456
#define N4_ALL (N4_X + N4_QK + N4_V + N4_O)

__global__ void cvt_all(const float4* __restrict__ x,
                        const float4* __restrict__ wqk,
                        const float4* __restrict__ wv,
                        const float4* __restrict__ wo) {
    int i = blockIdx.x * 256 + threadIdx.x;
    const float4* src;
    __half2* dst;
    int j;
    if (i < N4_X) { src = x; dst = (__half2*)g_xt; j = i; }
    else if (i < N4_X + N4_QK) { src = wqk; dst = (__half2*)g_wqkt; j = i - N4_X; }
    else if (i < N4_X + N4_QK + N4_V) { src = wv; dst = (__half2*)g_wvt; j = i - N4_X - N4_QK; }
    else { src = wo; dst = (__half2*)g_wot; j = i - N4_X - N4_QK - N4_V; }
    float4 v = src[j];
    dst[2 * j]     = __floats2half2_rn(v.x, v.y);
    dst[2 * j + 1] = __floats2half2_rn(v.z, v.w);
}

// ---------------------------------------------------------------------------
// fp16 tensor-core GEMM, BK=64, 3-stage cp.async (issue interleaved with
// compute), block 256x128, 256 threads = 8 warps (4x2), warp tile 64x64.
// MODE 0: A = g_xt; blocks x<12 -> QK proj, x>=12 -> V proj; smem-staged
//         coalesced epilogue (Q scaled by log2e).
// MODE 2: A = g_O2 (dense), W = g_wot, result -> out (fp32 direct).
// ---------------------------------------------------------------------------
#define BM 256
#define BN 128
#define NT2 12                               // 768 / 64
#define SSTH 72                              // padded row stride (halves)
#define STG_BYTES ((BM + BN) * SSTH * 2)     // 55296
#define GEMM_SMEM (3 * STG_BYTES)            // 165888
#define EPST 136                             // epilogue smem row stride (halves)

template <int MODE>
__global__ void __launch_bounds__(256, 1)
mma_gemm(const float* __restrict__ b0, const float* __restrict__ b1,
         float* __restrict__ out) {
    extern __shared__ uint32_t dsm[];
    const uint32_t smb = smem_u32(dsm);
    const int tid = threadIdx.x;
    const int lane = tid & 31;
    const int wid = tid >> 5;
    const int g = lane >> 2;
    const int t = lane & 3;
    const int wr = wid >> 1;      // 0..3 (64-row band)
    const int wc = wid & 1;       // 0..1 (64-col band)
    const int m0 = blockIdx.y * BM;

    const __half* Abase = (MODE == 0) ? g_xt : g_O2;
    const __half* W;
    const float* bias;
    int ncol0;
    int isV = 0;
    if (MODE == 0) {
        if (blockIdx.x < 12) { W = g_wqkt; bias = b0; ncol0 = blockIdx.x * BN; }
        else { W = g_wvt; bias = b1; ncol0 = (blockIdx.x - 12) * BN; isV = 1; }
    } else {
        W = g_wot; bias = b0; ncol0 = blockIdx.x * BN;
    }

    float acc[4][8][4];
#pragma unroll
    for (int mi = 0; mi < 4; mi++)
#pragma unroll
        for (int ni = 0; ni < 8; ni++)
#pragma unroll
            for (int r = 0; r < 4; r++) acc[mi][ni][r] = 0.0f;

    const uint32_t aoffA = lda_off_h(lane, SSTH);
    const uint32_t boffB = ldb_off_h(lane, SSTH);

    // A: 256x64h = 2048 16B-chunks (8/thread); B: 128x64h = 1024 (4/thread)
#define ISSUE_A(kt, st, ii)                                                    \
    do {                                                                       \
        int c = tid + (ii) * 256;                                              \
        int r = c >> 3, q = (c & 7) * 8;                                       \
        cpa16(smb + (st) * STG_BYTES + (uint32_t)((r * SSTH + q) * 2),         \
              Abase + (size_t)(m0 + r) * DMODEL + (kt) * 64 + q);              \
    } while (0)
#define ISSUE_B(kt, st, ii)                                                    \
    do {                                                                       \
        int c = tid + (ii) * 256;                                              \
        int r = c >> 3, q = (c & 7) * 8;                                       \
        cpa16(smb + (st) * STG_BYTES + (uint32_t)(((BM + r) * SSTH + q) * 2),  \
              W + (size_t)(ncol0 + r) * DMODEL + (kt) * 64 + q);               \
    } while (0)
#define ISSUE_PART(kt, st, p)                                                  \
    do { ISSUE_A(kt, st, 2 * (p)); ISSUE_A(kt, st, 2 * (p) + 1);               \
         ISSUE_B(kt, st, p); } while (0)
#define ISSUE_TILE(kt, st)                                                     \
    do { ISSUE_PART(kt, st, 0); ISSUE_PART(kt, st, 1);                         \
         ISSUE_PART(kt, st, 2); ISSUE_PART(kt, st, 3); } while (0)

    ISSUE_TILE(0, 0); CP_COMMIT();
    ISSUE_TILE(1, 1); CP_COMMIT();

    for (int kt = 0; kt < NT2; kt++) {
        if (kt < NT2 - 1) { CP_WAIT1(); } else { CP_WAIT0(); }
        __syncthreads();              // tile kt ready; stage (kt+2)%3 free

        const int pre = (kt + 2 < NT2);
        const int pkt = kt + 2;
        const int pst = (kt + 2) % 3;
        const uint32_t stB = smb + (kt % 3) * STG_BYTES;
        const uint32_t aA = stB + (uint32_t)(wr * 64 * SSTH * 2) + aoffA;
        const uint32_t aB = stB + (uint32_t)((BM + wc * 64) * SSTH * 2) + boffB;

#pragma unroll
        for (int ks = 0; ks < 4; ks++) {
            if (pre) ISSUE_PART(pkt, pst, ks);   // overlap LSU with MMAs
            const uint32_t kb = ks * 32;          // 16 halves
            uint32_t bf[8][2];
#pragma unroll
            for (int j = 0; j < 4; j++) {
                uint32_t r[4];
                ldm_x4(r, aB + (uint32_t)(j * 16 * SSTH * 2) + kb);
                bf[2 * j][0] = r[0];     bf[2 * j][1] = r[1];
                bf[2 * j + 1][0] = r[2]; bf[2 * j + 1][1] = r[3];
            }
#pragma unroll
            for (int mi = 0; mi < 4; mi++) {
                uint32_t af[4];
                ldm_x4(af, aA + (uint32_t)(mi * 16 * SSTH * 2) + kb);
#pragma unroll
                for (int ni = 0; ni < 8; ni++)
                    MMA_F16(acc[mi][ni], af, bf[ni]);
            }
        }
        if (pre) CP_COMMIT();
    }
#undef ISSUE_TILE
#undef ISSUE_PART
#undef ISSUE_B
#undef ISSUE_A

    // ---- epilogue ----
    if (MODE == 2) {
#pragma unroll
        for (int ni = 0; ni < 8; ni++) {
            int gc = ncol0 + wc * 64 + ni * 8 + 2 * t;
            float bb0 = bias[gc], bb1 = bias[gc + 1];
#pragma unroll
            for (int mi = 0; mi < 4; mi++) {
                int r_lo = m0 + wr * 64 + mi * 16 + g;
                out[(size_t)r_lo * DMODEL + gc]           = acc[mi][ni][0] + bb0;
                out[(size_t)r_lo * DMODEL + gc + 1]       = acc[mi][ni][1] + bb1;
                out[(size_t)(r_lo + 8) * DMODEL + gc]     = acc[mi][ni][2] + bb0;
                out[(size_t)(r_lo + 8) * DMODEL + gc + 1] = acc[mi][ni][3] + bb1;
            }
        }
    } else {
        __syncthreads();                 // stage buffers free for reuse
        __half* ep = (__half*)dsm;       // [256][EPST] = 69632 B
        const float qs = isV ? 1.0f : LOG2E;
#pragma unroll
        for (int ni = 0; ni < 8; ni++) {
            int lc = wc * 64 + ni * 8 + 2 * t;
            int gc = ncol0 + lc;
            float bb0 = bias[gc], bb1 = bias[gc + 1];
#pragma unroll
            for (int mi = 0; mi < 4; mi++) {
                int rl = wr * 64 + mi * 16 + g;
                *(__half2*)&ep[rl * EPST + lc] = __floats2half2_rn(
                    (acc[mi][ni][0] + bb0) * qs, acc[mi][ni][1] + bb1);
                *(__half2*)&ep[(rl + 8) * EPST + lc] = __floats2half2_rn(
                    (acc[mi][ni][2] + bb0) * qs, acc[mi][ni][3] + bb1);
            }
        }
        __syncthreads();

        if (!isV) {
            // QK block: one head h0; word w of a row = (Q[w], K[w])
            const int h0 = ncol0 >> 7;
#pragma unroll
            for (int i = 0; i < 8; i++) {
                int c = tid + i * 256;               // 0..2047
                int row = c >> 3, e0 = (c & 7) * 8;
                int m = m0 + row, bb = m >> 10, nn = m & 1023;
                const uint32_t* src = (const uint32_t*)&ep[row * EPST] + e0;
                uint32_t u[8];
#pragma unroll
                for (int j = 0; j < 8; j++) u[j] = src[j];
                uint4 qv, kv;
                qv.x = __byte_perm(u[0], u[1], 0x5410);
                qv.y = __byte_perm(u[2], u[3], 0x5410);
                qv.z = __byte_perm(u[4], u[5], 0x5410);
                qv.w = __byte_perm(u[6], u[7], 0x5410);
                kv.x = __byte_perm(u[0], u[1], 0x7632);
                kv.y = __byte_perm(u[2], u[3], 0x7632);
                kv.z = __byte_perm(u[4], u[5], 0x7632);
                kv.w = __byte_perm(u[6], u[7], 0x7632);
                size_t base = ((size_t)(bb * NHEAD + h0) * SEQ + nn) * EDIM + e0;
                *(uint4*)(g_Q + base) = qv;
                *(uint4*)(g_K + base) = kv;
            }
        } else {
            // V block: two dense head tiles
            const int hA = ncol0 >> 6;
#pragma unroll
            for (int i = 0; i < 16; i++) {
                int c = tid + i * 256;               // 0..4095
                int row = c >> 4, ch = c & 15;
                int m = m0 + row, bb = m >> 10, nn = m & 1023;
                uint4 v = *(const uint4*)&ep[row * EPST + ch * 8];
                int h = hA + (ch >> 3), e0 = (ch * 8) & 63;
                *(uint4*)(g_V + ((size_t)(bb * NHEAD + h) * SEQ + nn) * EDIM + e0) = v;
            }
        }
    }
}

// ---------------------------------------------------------------------------
// fp16 flash attention, 128-query tiles, 256 threads (8 warps), 2 CTAs/SM.
// P in registers; 3-stage cp.async K/V; exp via ex2 (Q pre-scaled by log2e).
// Output written DENSE into g_O2 [M x 768].  (unchanged)
// ---------------------------------------------------------------------------
#define KSTH 72
#define KVH (2 * 64 * KSTH)                  // halves per stage = 9216
#define AT_SMEM (3 * KVH * 2)                // 55296 B
#define NKT (SEQ / 64)                       // 16 key tiles

__global__ void __launch_bounds__(256, 2) attn_tc() {
    extern __shared__ __half smh[];
    const uint32_t smb = smem_u32(smh);

    const int tid = threadIdx.x;
    const int lane = tid & 31;
    const int wid = tid >> 5;
    const int g = lane >> 2;
    const int t = lane & 3;
    const int r0 = wid * 16;          // warp's query-row base (0..112)
    const int qt = blockIdx.x;        // 0..7
    const int h  = blockIdx.y;
    const int b  = blockIdx.z;
    const int bh = b * NHEAD + h;

    const uint32_t* Qw =
        (const uint32_t*)(g_Q + ((size_t)bh * SEQ + qt * 128) * EDIM);
    const __half* Kg0 = g_K + (size_t)bh * SEQ * EDIM;
    const __half* Vg0 = g_V + (size_t)bh * SEQ * EDIM;

    // Q fragments (fp16 pairs), 16 regs
    uint32_t qf[4][4];
#pragma unroll
    for (int ks = 0; ks < 4; ks++) {
        qf[ks][0] = Qw[(r0 + g) * 32 + ks * 8 + t];
        qf[ks][1] = Qw[(r0 + g + 8) * 32 + ks * 8 + t];
        qf[ks][2] = Qw[(r0 + g) * 32 + ks * 8 + t + 4];
        qf[ks][3] = Qw[(r0 + g + 8) * 32 + ks * 8 + t + 4];
    }

    const uint32_t boffK = ldb_off_h(lane, KSTH);
    const uint32_t aoffV = lda_off_h(lane, KSTH);

#define ISSUE_KV(kt, st)                                                       \
    do {                                                                       \
        const __half* Kg = Kg0 + (kt) * 64 * EDIM;                             \
        const __half* Vg = Vg0 + (kt) * 64 * EDIM;                             \
        _Pragma("unroll") for (int i = 0; i < 2; i++) {                        \
            int c = tid + i * 256;                                             \
            int row = c >> 3, q = (c & 7) * 8;                                 \
            cpa16(smb + (uint32_t)(((st) * KVH + row * KSTH + q) * 2),         \
                  Kg + row * EDIM + q);                                        \
            cpa16(smb + (uint32_t)(((st) * KVH + 64 * KSTH + row * KSTH + q) * 2),\
                  Vg + row * EDIM + q);                                        \
        }                                                                      \
    } while (0)

    ISSUE_KV(0, 0); CP_COMMIT();
    ISSUE_KV(1, 1); CP_COMMIT();

    float o[8][4];
#pragma unroll
    for (int ni = 0; ni < 8; ni++)
#pragma unroll
        for (int r = 0; r < 4; r++) o[ni][r] = 0.0f;
    float mrow0 = -1e30f, mrow1 = -1e30f, l0 = 0.0f, l1 = 0.0f;

    for (int kt = 0; kt < NKT; kt++) {
        if (kt < NKT - 1) { CP_WAIT1(); } else { CP_WAIT0(); }
        __syncthreads();             // tile kt visible; stage (kt+2)%3 free
        if (kt + 2 < NKT) { ISSUE_KV(kt + 2, (kt + 2) % 3); CP_COMMIT(); }
        const uint32_t ksb = smb + (uint32_t)((kt % 3) * KVH * 2);
        const uint32_t vsb = ksb + (uint32_t)(64 * KSTH * 2);

        // ---- S = Q @ K^T  (log2 domain) ----
        float s[8][4];
#pragma unroll
        for (int ni = 0; ni < 8; ni++)
#pragma unroll
            for (int r = 0; r < 4; r++) s[ni][r] = 0.0f;
#pragma unroll
        for (int ks = 0; ks < 4; ks++) {
            const uint32_t kb = ks * 32;
#pragma unroll
            for (int j = 0; j < 4; j++) {
                uint32_t r[4];
                ldm_x4(r, ksb + boffK + (uint32_t)(j * 16 * KSTH * 2) + kb);
                uint32_t bf0[2] = {r[0], r[1]};
                uint32_t bf1[2] = {r[2], r[3]};
                MMA_F16(s[2 * j],     qf[ks], bf0);
                MMA_F16(s[2 * j + 1], qf[ks], bf1);
            }
        }

        // ---- online softmax (2^x domain); P packed into A-fragments ----
        float mx0 = -1e30f, mx1 = -1e30f;
#pragma unroll
        for (int ni = 0; ni < 8; ni++) {
            mx0 = fmaxf(mx0, fmaxf(s[ni][0], s[ni][1]));
            mx1 = fmaxf(mx1, fmaxf(s[ni][2], s[ni][3]));
        }
        mx0 = fmaxf(mx0, __shfl_xor_sync(0xffffffffu, mx0, 1));
        mx0 = fmaxf(mx0, __shfl_xor_sync(0xffffffffu, mx0, 2));
        mx1 = fmaxf(mx1, __shfl_xor_sync(0xffffffffu, mx1, 1));
        mx1 = fmaxf(mx1, __shfl_xor_sync(0xffffffffu, mx1, 2));
        float mn0 = fmaxf(mrow0, mx0), mn1 = fmaxf(mrow1, mx1);
        float al0 = ex2(mrow0 - mn0), al1 = ex2(mrow1 - mn1);
        mrow0 = mn0; mrow1 = mn1;
        float sum0 = 0.0f, sum1 = 0.0f;
        uint32_t pf[4][4];
#pragma unroll
        for (int ni = 0; ni < 8; ni++) {
            float p0 = ex2(s[ni][0] - mn0);
            float p1 = ex2(s[ni][1] - mn0);
            float p2 = ex2(s[ni][2] - mn1);
            float p3 = ex2(s[ni][3] - mn1);
            sum0 += p0 + p1;
            sum1 += p2 + p3;
            o[ni][0] *= al0; o[ni][1] *= al0;
            o[ni][2] *= al1; o[ni][3] *= al1;
            int ks = ni >> 1;
            uint32_t lo = packh2(p0, p1);
            uint32_t hi = packh2(p2, p3);
            if (ni & 1) { pf[ks][2] = lo; pf[ks][3] = hi; }
            else        { pf[ks][0] = lo; pf[ks][1] = hi; }
        }
        sum0 += __shfl_xor_sync(0xffffffffu, sum0, 1);
        sum0 += __shfl_xor_sync(0xffffffffu, sum0, 2);
        sum1 += __shfl_xor_sync(0xffffffffu, sum1, 1);
        sum1 += __shfl_xor_sync(0xffffffffu, sum1, 2);
        l0 = l0 * al0 + sum0;
        l1 = l1 * al1 + sum1;

        // ---- O += P @ V (P in registers, V via ldmatrix.trans) ----
#pragma unroll
        for (int ks = 0; ks < 4; ks++) {
#pragma unroll
            for (int j = 0; j < 4; j++) {
                uint32_t r[4];
                ldm_x4_t(r, vsb + aoffV +
                            (uint32_t)((ks * 16 * KSTH + j * 16) * 2));
                uint32_t bf0[2] = {r[0], r[1]};
                uint32_t bf1[2] = {r[2], r[3]};
                MMA_F16(o[2 * j],     pf[ks], bf0);
                MMA_F16(o[2 * j + 1], pf[ks], bf1);
            }
        }
    }
#undef ISSUE_KV

    // ---- finalize: write DENSE rows of g_O2 [M x 768] ----
    float inv0 = 1.0f / (l0 * SOFTMAX_DIV);
    float inv1 = 1.0f / (l1 * SOFTMAX_DIV);

    __half* Ob = g_O2 + (size_t)(b * SEQ + qt * 128) * DMODEL + h * EDIM;
#pragma unroll
    for (int ni = 0; ni < 8; ni++) {
        *(__half2*)&Ob[(size_t)(r0 + g) * DMODEL + ni * 8 + 2 * t] =
            __floats2half2_rn(o[ni][0] * inv0, o[ni][1] * inv0);
        *(__half2*)&Ob[(size_t)(r0 + g + 8) * DMODEL + ni * 8 + 2 * t] =
            __floats2half2_rn(o[ni][2] * inv1, o[ni][3] * inv1);
    }
}

// ---------------------------------------------------------------------------
// kernel_launch
// ---------------------------------------------------------------------------
extern "C" void kernel_launch(void* const* d_in, const int* in_sizes, int n_in,
                              void* d_out, int out_size) {
    const float* x      = (const float*)d_in[0];
    const float* Wqk_w  = (const float*)d_in[1];
    const float* Wqk_b  = (const float*)d_in[2];
    const float* Wv_w   = (const float*)d_in[3];
    const float* Wv_b   = (const float*)d_in[4];
    const float* Wo_w   = (const float*)d_in[5];
    const float* Wo_b   = (const float*)d_in[6];
    float* out = (float*)d_out;

    (void)in_sizes; (void)n_in; (void)out_size;

    cudaFuncSetAttribute(mma_gemm<0>, cudaFuncAttributeMaxDynamicSharedMemorySize, GEMM_SMEM);
    cudaFuncSetAttribute(mma_gemm<2>, cudaFuncAttributeMaxDynamicSharedMemorySize, GEMM_SMEM);
    cudaFuncSetAttribute(attn_tc, cudaFuncAttributeMaxDynamicSharedMemorySize, AT_SMEM);

    // 0) pre-round x / weights to fp16
    cvt_all<<<N4_ALL / 256, 256>>>((const float4*)x, (const float4*)Wqk_w,
                                   (const float4*)Wv_w, (const float4*)Wo_w);
    // 1) fused QKV projections -> g_Q (log2e-scaled), g_K, g_V
    mma_gemm<0><<<dim3(18, 64), 256, GEMM_SMEM>>>(Wqk_b, Wv_b, nullptr);
    // 2) attention -> g_O2 (dense concat)
    attn_tc<<<dim3(SEQ / 128, NHEAD, BSZ), 256, AT_SMEM>>>();
    // 3) output projection -> d_out
    mma_gemm<2><<<dim3(6, 64), 256, GEMM_SMEM>>>(Wo_b, nullptr, out);
}

// round 17
// speedup vs baseline: 1.0580x; 1.0181x over previous
#include <cuda_runtime.h>
#include <cuda_fp16.h>
#include <cstdint>
#include <math.h>

// ---------------------------------------------------------------------------
// Problem constants
// ---------------------------------------------------------------------------
#define BSZ 16
#define SEQ 1024
#define DMODEL 768
#define NHEAD 12
#define EDIM 64
#define SOFTMAX_DIV 27.712812921102035f
#define LOG2E 1.4426950408889634f

#define BHNE (BSZ * NHEAD * SEQ * EDIM)
__device__ __half g_Q[BHNE];                    // pre-scaled by log2(e)
__device__ __half g_K[BHNE];
__device__ __half g_V[BHNE];
__device__ __half g_O2[BSZ * SEQ * DMODEL];     // dense concat matrix

// pre-converted fp16 operands
__device__ __half g_xt[BSZ * SEQ * DMODEL];
__device__ __half g_wqkt[2 * DMODEL * DMODEL];
__device__ __half g_wvt[DMODEL * DMODEL];
__device__ __half g_wot[DMODEL * DMODEL];

// ---------------------------------------------------------------------------
// helpers (plain sm_80+ PTX only)
// ---------------------------------------------------------------------------
__device__ __forceinline__ uint32_t smem_u32(const void* p) {
    uint32_t a;
    asm("{ .reg .u64 t; cvta.to.shared.u64 t, %1; cvt.u32.u64 %0, t; }"
        : "=r"(a) : "l"(p));
    return a;
}
__device__ __forceinline__ void cpa16(uint32_t dst, const void* src) {
    asm volatile("cp.async.cg.shared.global [%0], [%1], 16;"
                 :: "r"(dst), "l"(src));
}
#define CP_COMMIT() asm volatile("cp.async.commit_group;" ::: "memory")
#define CP_WAIT0()  asm volatile("cp.async.wait_group 0;" ::: "memory")
#define CP_WAIT1()  asm volatile("cp.async.wait_group 1;" ::: "memory")

__device__ __forceinline__ float ex2(float x) {
    float y;
    asm("ex2.approx.f32 %0, %1;" : "=f"(y) : "f"(x));
    return y;
}
// packed fp16x2 exp2 -- one MUFU op per PAIR, result is a ready A-frag word
__device__ __forceinline__ uint32_t ex2h2(uint32_t x) {
    uint32_t y;
    asm("ex2.approx.f16x2 %0, %1;" : "=r"(y) : "r"(x));
    return y;
}

#define MMA_F16(acc, af, bf)                                                   \
    asm volatile(                                                              \
        "mma.sync.aligned.m16n8k16.row.col.f32.f16.f16.f32 "                   \
        "{%0,%1,%2,%3}, {%4,%5,%6,%7}, {%8,%9}, {%0,%1,%2,%3};"                \
        : "+f"((acc)[0]), "+f"((acc)[1]), "+f"((acc)[2]), "+f"((acc)[3])       \
        : "r"((af)[0]), "r"((af)[1]), "r"((af)[2]), "r"((af)[3]),              \
          "r"((bf)[0]), "r"((bf)[1]))

__device__ __forceinline__ void ldm_x4(uint32_t* r, uint32_t addr) {
    asm volatile(
        "ldmatrix.sync.aligned.m8n8.x4.shared.b16 {%0,%1,%2,%3}, [%4];"
        : "=r"(r[0]), "=r"(r[1]), "=r"(r[2]), "=r"(r[3]) : "r"(addr));
}
__device__ __forceinline__ void ldm_x4_t(uint32_t* r, uint32_t addr) {
    asm volatile(
        "ldmatrix.sync.aligned.m8n8.x4.trans.shared.b16 {%0,%1,%2,%3}, [%4];"
        : "=r"(r[0]), "=r"(r[1]), "=r"(r[2]), "=r"(r[3]) : "r"(addr));
}
// A-style x4: matrices (R,k0),(R+8,k0),(R,k8),(R+8,k8)  (ST in halves)
__device__ __forceinline__ uint32_t lda_off_h(int lane, int ST) {
    int row = (lane & 7) + ((lane >> 3) & 1) * 8;
    int koff = ((lane >> 4) & 1) * 8;
    return (uint32_t)((row * ST + koff) * 2);
}
// B-style x4: matrices (N,k0),(N,k8),(N+8,k0),(N+8,k8)
__device__ __forceinline__ uint32_t ldb_off_h(int lane, int ST) {
    int row = (lane & 7) + ((lane >> 4) & 1) * 8;
    int koff = ((lane >> 3) & 1) * 8;
    return (uint32_t)((row * ST + koff) * 2);
}
__device__ __forceinline__ uint32_t packh2(float a, float b) {
    __half2 h = __floats2half2_rn(a, b);
    return *reinterpret_cast<uint32_t*>(&h);
}

// ---------------------------------------------------------------------------
// One-shot fp16 pre-conversion of x, Wqk, Wv, Wo
// ---------------------------------------------------------------------------
#define N4_X   3145728
#define N4_QK  294912
#define N4_V   147456
#define N4_O   147456
#define N4_ALL (N4_X + N4_QK + N4_V + N4_O)

__global__ void cvt_all(const float4* __restrict__ x,
                        const float4* __restrict__ wqk,
                        const float4* __restrict__ wv,
                        const float4* __restrict__ wo) {
    int i = blockIdx.x * 256 + threadIdx.x;
    const float4* src;
    __half2* dst;
    int j;
    if (i < N4_X) { src = x; dst = (__half2*)g_xt; j = i; }
    else if (i < N4_X + N4_QK) { src = wqk; dst = (__half2*)g_wqkt; j = i - N4_X; }
    else if (i < N4_X + N4_QK + N4_V) { src = wv; dst = (__half2*)g_wvt; j = i - N4_X - N4_QK; }
    else { src = wo; dst = (__half2*)g_wot; j = i - N4_X - N4_QK - N4_V; }
    float4 v = src[j];
    dst[2 * j]     = __floats2half2_rn(v.x, v.y);
    dst[2 * j + 1] = __floats2half2_rn(v.z, v.w);
}

// ---------------------------------------------------------------------------
// fp16 tensor-core GEMM, BK=64, 3-stage cp.async (issue interleaved with
// compute), block 256x128, 256 threads = 8 warps (4x2), warp tile 64x64.
// MODE 0: A = g_xt; blocks x<12 -> QK proj, x>=12 -> V proj; smem-staged
//         coalesced epilogue (Q scaled by log2e).
// MODE 2: A = g_O2 (dense), W = g_wot, result -> out (fp32 direct).
// ---------------------------------------------------------------------------
#define BM 256
#define BN 128
#define NT2 12                               // 768 / 64
#define SSTH 72                              // padded row stride (halves)
#define STG_BYTES ((BM + BN) * SSTH * 2)     // 55296
#define GEMM_SMEM (3 * STG_BYTES)            // 165888
#define EPST 136                             // epilogue smem row stride (halves)

template <int MODE>
__global__ void __launch_bounds__(256, 1)
mma_gemm(const float* __restrict__ b0, const float* __restrict__ b1,
         float* __restrict__ out) {
    extern __shared__ uint32_t dsm[];
    const uint32_t smb = smem_u32(dsm);
    const int tid = threadIdx.x;
    const int lane = tid & 31;
    const int wid = tid >> 5;
    const int g = lane >> 2;
    const int t = lane & 3;
    const int wr = wid >> 1;      // 0..3 (64-row band)
    const int wc = wid & 1;       // 0..1 (64-col band)
    const int m0 = blockIdx.y * BM;

    const __half* Abase = (MODE == 0) ? g_xt : g_O2;
    const __half* W;
    const float* bias;
    int ncol0;
    int isV = 0;
    if (MODE == 0) {
        if (blockIdx.x < 12) { W = g_wqkt; bias = b0; ncol0 = blockIdx.x * BN; }
        else { W = g_wvt; bias = b1; ncol0 = (blockIdx.x - 12) * BN; isV = 1; }
    } else {
        W = g_wot; bias = b0; ncol0 = blockIdx.x * BN;
    }

    float acc[4][8][4];
#pragma unroll
    for (int mi = 0; mi < 4; mi++)
#pragma unroll
        for (int ni = 0; ni < 8; ni++)
#pragma unroll
            for (int r = 0; r < 4; r++) acc[mi][ni][r] = 0.0f;

    const uint32_t aoffA = lda_off_h(lane, SSTH);
    const uint32_t boffB = ldb_off_h(lane, SSTH);

    // A: 256x64h = 2048 16B-chunks (8/thread); B: 128x64h = 1024 (4/thread)
#define ISSUE_A(kt, st, ii)                                                    \
    do {                                                                       \
        int c = tid + (ii) * 256;                                              \
        int r = c >> 3, q = (c & 7) * 8;                                       \
        cpa16(smb + (st) * STG_BYTES + (uint32_t)((r * SSTH + q) * 2),         \
              Abase + (size_t)(m0 + r) * DMODEL + (kt) * 64 + q);              \
    } while (0)
#define ISSUE_B(kt, st, ii)                                                    \
    do {                                                                       \
        int c = tid + (ii) * 256;                                              \
        int r = c >> 3, q = (c & 7) * 8;                                       \
        cpa16(smb + (st) * STG_BYTES + (uint32_t)(((BM + r) * SSTH + q) * 2),  \
              W + (size_t)(ncol0 + r) * DMODEL + (kt) * 64 + q);               \
    } while (0)
#define ISSUE_PART(kt, st, p)                                                  \
    do { ISSUE_A(kt, st, 2 * (p)); ISSUE_A(kt, st, 2 * (p) + 1);               \
         ISSUE_B(kt, st, p); } while (0)
#define ISSUE_TILE(kt, st)                                                     \
    do { ISSUE_PART(kt, st, 0); ISSUE_PART(kt, st, 1);                         \
         ISSUE_PART(kt, st, 2); ISSUE_PART(kt, st, 3); } while (0)

    ISSUE_TILE(0, 0); CP_COMMIT();
    ISSUE_TILE(1, 1); CP_COMMIT();

    for (int kt = 0; kt < NT2; kt++) {
        if (kt < NT2 - 1) { CP_WAIT1(); } else { CP_WAIT0(); }
        __syncthreads();              // tile kt ready; stage (kt+2)%3 free

        const int pre = (kt + 2 < NT2);
        const int pkt = kt + 2;
        const int pst = (kt + 2) % 3;
        const uint32_t stB = smb + (kt % 3) * STG_BYTES;
        const uint32_t aA = stB + (uint32_t)(wr * 64 * SSTH * 2) + aoffA;
        const uint32_t aB = stB + (uint32_t)((BM + wc * 64) * SSTH * 2) + boffB;

#pragma unroll
        for (int ks = 0; ks < 4; ks++) {
            if (pre) ISSUE_PART(pkt, pst, ks);   // overlap LSU with MMAs
            const uint32_t kb = ks * 32;          // 16 halves
            uint32_t bf[8][2];
#pragma unroll
            for (int j = 0; j < 4; j++) {
                uint32_t r[4];
                ldm_x4(r, aB + (uint32_t)(j * 16 * SSTH * 2) + kb);
                bf[2 * j][0] = r[0];     bf[2 * j][1] = r[1];
                bf[2 * j + 1][0] = r[2]; bf[2 * j + 1][1] = r[3];
            }
#pragma unroll
            for (int mi = 0; mi < 4; mi++) {
                uint32_t af[4];
                ldm_x4(af, aA + (uint32_t)(mi * 16 * SSTH * 2) + kb);
#pragma unroll
                for (int ni = 0; ni < 8; ni++)
                    MMA_F16(acc[mi][ni], af, bf[ni]);
            }
        }
        if (pre) CP_COMMIT();
    }
#undef ISSUE_TILE
#undef ISSUE_PART
#undef ISSUE_B
#undef ISSUE_A

    // ---- epilogue ----
    if (MODE == 2) {
#pragma unroll
        for (int ni = 0; ni < 8; ni++) {
            int gc = ncol0 + wc * 64 + ni * 8 + 2 * t;
            float bb0 = bias[gc], bb1 = bias[gc + 1];
#pragma unroll
            for (int mi = 0; mi < 4; mi++) {
                int r_lo = m0 + wr * 64 + mi * 16 + g;
                out[(size_t)r_lo * DMODEL + gc]           = acc[mi][ni][0] + bb0;
                out[(size_t)r_lo * DMODEL + gc + 1]       = acc[mi][ni][1] + bb1;
                out[(size_t)(r_lo + 8) * DMODEL + gc]     = acc[mi][ni][2] + bb0;
                out[(size_t)(r_lo + 8) * DMODEL + gc + 1] = acc[mi][ni][3] + bb1;
            }
        }
    } else {
        __syncthreads();                 // stage buffers free for reuse
        __half* ep = (__half*)dsm;       // [256][EPST] = 69632 B
        const float qs = isV ? 1.0f : LOG2E;
#pragma unroll
        for (int ni = 0; ni < 8; ni++) {
            int lc = wc * 64 + ni * 8 + 2 * t;
            int gc = ncol0 + lc;
            float bb0 = bias[gc], bb1 = bias[gc + 1];
#pragma unroll
            for (int mi = 0; mi < 4; mi++) {
                int rl = wr * 64 + mi * 16 + g;
                *(__half2*)&ep[rl * EPST + lc] = __floats2half2_rn(
                    (acc[mi][ni][0] + bb0) * qs, acc[mi][ni][1] + bb1);
                *(__half2*)&ep[(rl + 8) * EPST + lc] = __floats2half2_rn(
                    (acc[mi][ni][2] + bb0) * qs, acc[mi][ni][3] + bb1);
            }
        }
        __syncthreads();

        if (!isV) {
            // QK block: one head h0; word w of a row = (Q[w], K[w])
            const int h0 = ncol0 >> 7;
#pragma unroll
            for (int i = 0; i < 8; i++) {
                int c = tid + i * 256;               // 0..2047
                int row = c >> 3, e0 = (c & 7) * 8;
                int m = m0 + row, bb = m >> 10, nn = m & 1023;
                const uint32_t* src = (const uint32_t*)&ep[row * EPST] + e0;
                uint32_t u[8];
#pragma unroll
                for (int j = 0; j < 8; j++) u[j] = src[j];
                uint4 qv, kv;
                qv.x = __byte_perm(u[0], u[1], 0x5410);
                qv.y = __byte_perm(u[2], u[3], 0x5410);
                qv.z = __byte_perm(u[4], u[5], 0x5410);
                qv.w = __byte_perm(u[6], u[7], 0x5410);
                kv.x = __byte_perm(u[0], u[1], 0x7632);
                kv.y = __byte_perm(u[2], u[3], 0x7632);
                kv.z = __byte_perm(u[4], u[5], 0x7632);
                kv.w = __byte_perm(u[6], u[7], 0x7632);
                size_t base = ((size_t)(bb * NHEAD + h0) * SEQ + nn) * EDIM + e0;
                *(uint4*)(g_Q + base) = qv;
                *(uint4*)(g_K + base) = kv;
            }
        } else {
            // V block: two dense head tiles
            const int hA = ncol0 >> 6;
#pragma unroll
            for (int i = 0; i < 16; i++) {
                int c = tid + i * 256;               // 0..4095
                int row = c >> 4, ch = c & 15;
                int m = m0 + row, bb = m >> 10, nn = m & 1023;
                uint4 v = *(const uint4*)&ep[row * EPST + ch * 8];
                int h = hA + (ch >> 3), e0 = (ch * 8) & 63;
                *(uint4*)(g_V + ((size_t)(bb * NHEAD + h) * SEQ + nn) * EDIM + e0) = v;
            }
        }
    }
}

// ---------------------------------------------------------------------------
// fp16 flash attention, 128-query tiles, 256 threads (8 warps), 2 CTAs/SM.
// P in registers; 3-stage cp.async K/V; P = ex2.approx.f16x2 (halves MUFU
// ops AND produces packed A-frag words directly). Q pre-scaled by log2e.
// Output written DENSE into g_O2 [M x 768].
// ---------------------------------------------------------------------------
#define KSTH 72
#define KVH (2 * 64 * KSTH)                  // halves per stage = 9216
#define AT_SMEM (3 * KVH * 2)                // 55296 B
#define NKT (SEQ / 64)                       // 16 key tiles

__global__ void __launch_bounds__(256, 2) attn_tc() {
    extern __shared__ __half smh[];
    const uint32_t smb = smem_u32(smh);

    const int tid = threadIdx.x;
    const int lane = tid & 31;
    const int wid = tid >> 5;
    const int g = lane >> 2;
    const int t = lane & 3;
    const int r0 = wid * 16;          // warp's query-row base (0..112)
    const int qt = blockIdx.x;        // 0..7
    const int h  = blockIdx.y;
    const int b  = blockIdx.z;
    const int bh = b * NHEAD + h;

    const uint32_t* Qw =
        (const uint32_t*)(g_Q + ((size_t)bh * SEQ + qt * 128) * EDIM);
    const __half* Kg0 = g_K + (size_t)bh * SEQ * EDIM;
    const __half* Vg0 = g_V + (size_t)bh * SEQ * EDIM;

    // Q fragments (fp16 pairs), 16 regs
    uint32_t qf[4][4];
#pragma unroll
    for (int ks = 0; ks < 4; ks++) {
        qf[ks][0] = Qw[(r0 + g) * 32 + ks * 8 + t];
        qf[ks][1] = Qw[(r0 + g + 8) * 32 + ks * 8 + t];
        qf[ks][2] = Qw[(r0 + g) * 32 + ks * 8 + t + 4];
        qf[ks][3] = Qw[(r0 + g + 8) * 32 + ks * 8 + t + 4];
    }

    const uint32_t boffK = ldb_off_h(lane, KSTH);
    const uint32_t aoffV = lda_off_h(lane, KSTH);

#define ISSUE_KV(kt, st)                                                       \
    do {                                                                       \
        const __half* Kg = Kg0 + (kt) * 64 * EDIM;                             \
        const __half* Vg = Vg0 + (kt) * 64 * EDIM;                             \
        _Pragma("unroll") for (int i = 0; i < 2; i++) {                        \
            int c = tid + i * 256;                                             \
            int row = c >> 3, q = (c & 7) * 8;                                 \
            cpa16(smb + (uint32_t)(((st) * KVH + row * KSTH + q) * 2),         \
                  Kg + row * EDIM + q);                                        \
            cpa16(smb + (uint32_t)(((st) * KVH + 64 * KSTH + row * KSTH + q) * 2),\
                  Vg + row * EDIM + q);                                        \
        }                                                                      \
    } while (0)

    ISSUE_KV(0, 0); CP_COMMIT();
    ISSUE_KV(1, 1); CP_COMMIT();

    float o[8][4];
#pragma unroll
    for (int ni = 0; ni < 8; ni++)
#pragma unroll
        for (int r = 0; r < 4; r++) o[ni][r] = 0.0f;
    float mrow0 = -1e30f, mrow1 = -1e30f, l0 = 0.0f, l1 = 0.0f;

    for (int kt = 0; kt < NKT; kt++) {
        if (kt < NKT - 1) { CP_WAIT1(); } else { CP_WAIT0(); }
        __syncthreads();             // tile kt visible; stage (kt+2)%3 free
        if (kt + 2 < NKT) { ISSUE_KV(kt + 2, (kt + 2) % 3); CP_COMMIT(); }
        const uint32_t ksb = smb + (uint32_t)((kt % 3) * KVH * 2);
        const uint32_t vsb = ksb + (uint32_t)(64 * KSTH * 2);

        // ---- S = Q @ K^T  (log2 domain) ----
        float s[8][4];
#pragma unroll
        for (int ni = 0; ni < 8; ni++)
#pragma unroll
            for (int r = 0; r < 4; r++) s[ni][r] = 0.0f;
#pragma unroll
        for (int ks = 0; ks < 4; ks++) {
            const uint32_t kb = ks * 32;
#pragma unroll
            for (int j = 0; j < 4; j++) {
                uint32_t r[4];
                ldm_x4(r, ksb + boffK + (uint32_t)(j * 16 * KSTH * 2) + kb);
                uint32_t bf0[2] = {r[0], r[1]};
                uint32_t bf1[2] = {r[2], r[3]};
                MMA_F16(s[2 * j],     qf[ks], bf0);
                MMA_F16(s[2 * j + 1], qf[ks], bf1);
            }
        }

        // ---- online softmax (2^x domain); P via packed f16x2 ex2 ----
        float mx0 = -1e30f, mx1 = -1e30f;
#pragma unroll
        for (int ni = 0; ni < 8; ni++) {
            mx0 = fmaxf(mx0, fmaxf(s[ni][0], s[ni][1]));
            mx1 = fmaxf(mx1, fmaxf(s[ni][2], s[ni][3]));
        }
        mx0 = fmaxf(mx0, __shfl_xor_sync(0xffffffffu, mx0, 1));
        mx0 = fmaxf(mx0, __shfl_xor_sync(0xffffffffu, mx0, 2));
        mx1 = fmaxf(mx1, __shfl_xor_sync(0xffffffffu, mx1, 1));
        mx1 = fmaxf(mx1, __shfl_xor_sync(0xffffffffu, mx1, 2));
        float mn0 = fmaxf(mrow0, mx0), mn1 = fmaxf(mrow1, mx1);
        float al0 = ex2(mrow0 - mn0), al1 = ex2(mrow1 - mn1);
        mrow0 = mn0; mrow1 = mn1;
        float sum0 = 0.0f, sum1 = 0.0f;
        uint32_t pf[4][4];
#pragma unroll
        for (int ni = 0; ni < 8; ni++) {
            // packed subtract+convert, then ONE f16x2 ex2 per pair
            uint32_t dlo = packh2(s[ni][0] - mn0, s[ni][1] - mn0);
            uint32_t dhi = packh2(s[ni][2] - mn1, s[ni][3] - mn1);
            uint32_t plo = ex2h2(dlo);
            uint32_t phi = ex2h2(dhi);
            float2 f0 = __half22float2(*reinterpret_cast<__half2*>(&plo));
            float2 f1 = __half22float2(*reinterpret_cast<__half2*>(&phi));
            sum0 += f0.x + f0.y;
            sum1 += f1.x + f1.y;
            o[ni][0] *= al0; o[ni][1] *= al0;
            o[ni][2] *= al1; o[ni][3] *= al1;
            int ks = ni >> 1;
            if (ni & 1) { pf[ks][2] = plo; pf[ks][3] = phi; }
            else        { pf[ks][0] = plo; pf[ks][1] = phi; }
        }
        sum0 += __shfl_xor_sync(0xffffffffu, sum0, 1);
        sum0 += __shfl_xor_sync(0xffffffffu, sum0, 2);
        sum1 += __shfl_xor_sync(0xffffffffu, sum1, 1);
        sum1 += __shfl_xor_sync(0xffffffffu, sum1, 2);
        l0 = l0 * al0 + sum0;
        l1 = l1 * al1 + sum1;

        // ---- O += P @ V (P in registers, V via ldmatrix.trans) ----
#pragma unroll
        for (int ks = 0; ks < 4; ks++) {
#pragma unroll
            for (int j = 0; j < 4; j++) {
                uint32_t r[4];
                ldm_x4_t(r, vsb + aoffV +
                            (uint32_t)((ks * 16 * KSTH + j * 16) * 2));
                uint32_t bf0[2] = {r[0], r[1]};
                uint32_t bf1[2] = {r[2], r[3]};
                MMA_F16(o[2 * j],     pf[ks], bf0);
                MMA_F16(o[2 * j + 1], pf[ks], bf1);
            }
        }
    }
#undef ISSUE_KV

    // ---- finalize: write DENSE rows of g_O2 [M x 768] ----
    float inv0 = 1.0f / (l0 * SOFTMAX_DIV);
    float inv1 = 1.0f / (l1 * SOFTMAX_DIV);

    __half* Ob = g_O2 + (size_t)(b * SEQ + qt * 128) * DMODEL + h * EDIM;
#pragma unroll
    for (int ni = 0; ni < 8; ni++) {
        *(__half2*)&Ob[(size_t)(r0 + g) * DMODEL + ni * 8 + 2 * t] =
            __floats2half2_rn(o[ni][0] * inv0, o[ni][1] * inv0);
        *(__half2*)&Ob[(size_t)(r0 + g + 8) * DMODEL + ni * 8 + 2 * t] =
            __floats2half2_rn(o[ni][2] * inv1, o[ni][3] * inv1);
    }
}

// ---------------------------------------------------------------------------
// kernel_launch
// ---------------------------------------------------------------------------
extern "C" void kernel_launch(void* const* d_in, const int* in_sizes, int n_in,
                              void* d_out, int out_size) {
    const float* x      = (const float*)d_in[0];
    const float* Wqk_w  = (const float*)d_in[1];
    const float* Wqk_b  = (const float*)d_in[2];
    const float* Wv_w   = (const float*)d_in[3];
    const float* Wv_b   = (const float*)d_in[4];
    const float* Wo_w   = (const float*)d_in[5];
    const float* Wo_b   = (const float*)d_in[6];
    float* out = (float*)d_out;

    (void)in_sizes; (void)n_in; (void)out_size;

    cudaFuncSetAttribute(mma_gemm<0>, cudaFuncAttributeMaxDynamicSharedMemorySize, GEMM_SMEM);
    cudaFuncSetAttribute(mma_gemm<2>, cudaFuncAttributeMaxDynamicSharedMemorySize, GEMM_SMEM);
    cudaFuncSetAttribute(attn_tc, cudaFuncAttributeMaxDynamicSharedMemorySize, AT_SMEM);

    // 0) pre-round x / weights to fp16
    cvt_all<<<N4_ALL / 256, 256>>>((const float4*)x, (const float4*)Wqk_w,
                                   (const float4*)Wv_w, (const float4*)Wo_w);
    // 1) fused QKV projections -> g_Q (log2e-scaled), g_K, g_V
    mma_gemm<0><<<dim3(18, 64), 256, GEMM_SMEM>>>(Wqk_b, Wv_b, nullptr);
    // 2) attention -> g_O2 (dense concat)
    attn_tc<<<dim3(SEQ / 128, NHEAD, BSZ), 256, AT_SMEM>>>();
    // 3) output projection -> d_out
    mma_gemm<2><<<dim3(6, 64), 256, GEMM_SMEM>>>(Wo_b, nullptr, out);
}